// round 14
// baseline (speedup 1.0000x reference)
#include <cuda_runtime.h>
#include <cstdint>

// GCNStage4_ReduceSum: out[t] += msg[e] for t = edge_index[1][e]
// msg: [NUM_EDGES, 32] f32; edge_index: [2, NUM_EDGES] int32 (harness); out: [num_nodes, 32] f32
//
// FINAL (converged, re-verified): atomic scatter at the validated sm_103a L2
// fp-RMW roofline. Evidence across 13 rounds:
//   - 7 structural variants (MLP sweep, occupancy sweep, lane relayout,
//     software pipeline, ELL gather, TMA cp.reduce.async.bulk, hybrid
//     concurrent paths) all converge to a ~46.5us scatter wall.
//   - Wall = 12.8M x 16B fp-add RMW ops at the shared per-16B L2 atomic ALU
//     (cp.reduce.async.bulk decomposes to the same micro-ops: R11 hybrid flat).
//   - DRAM traffic measured == compulsory 228MB; no wasted bytes.
//   - This exact shape measured fastest and reproduced twice (47.584us).
//
// Shape: 8 lanes = one 128B edge row (RED.128 warp-op touches 4 lines),
// unroll-4 grid-stride with front-batched loads (MLP~8 per thread),
// fire-and-forget red.global.add.v4.f32, cudaMemsetAsync zero-fill.

#define FEAT 32
#define UNROLL 4

__global__ void __launch_bounds__(256) scatter_add_kernel(
        const float4* __restrict__ msg4,
        const int* __restrict__ tgt,
        float* __restrict__ out,
        int num_frags)   // num_edges * 8
{
    int tid = blockIdx.x * blockDim.x + threadIdx.x;
    int stride = gridDim.x * blockDim.x;

    int   t[UNROLL];
    float4 v[UNROLL];
    int   id[UNROLL];

    // Phase 1: issue all loads (front-batched -> high MLP)
    #pragma unroll
    for (int u = 0; u < UNROLL; u++) {
        id[u] = tid + u * stride;
        if (id[u] < num_frags) {
            int e   = id[u] >> 3;
            int sub = id[u] & 7;
            t[u] = tgt[e];                                   // broadcast across 8 lanes
            v[u] = __ldcs(&msg4[(size_t)e * 8 + sub]);       // coalesced 128B row
        }
    }

    // Phase 2: fire-and-forget vector reductions (resolve at L2)
    #pragma unroll
    for (int u = 0; u < UNROLL; u++) {
        if (id[u] < num_frags) {
            int sub = id[u] & 7;
            float* dst = out + (size_t)t[u] * FEAT + sub * 4;
            asm volatile("red.global.add.v4.f32 [%0], {%1, %2, %3, %4};"
                         :: "l"(dst), "f"(v[u].x), "f"(v[u].y), "f"(v[u].z), "f"(v[u].w)
                         : "memory");
        }
    }
}

extern "C" void kernel_launch(void* const* d_in, const int* in_sizes, int n_in,
                              void* d_out, int out_size) {
    const float4* msg4 = (const float4*)d_in[0];
    const int*    ei   = (const int*)d_in[1];   // int32 indices
    float*        out  = (float*)d_out;

    int num_edges = in_sizes[0] / FEAT;          // 1,600,000
    const int* tgt = ei + num_edges;             // row 1 of edge_index

    // 1) zero the output (poisoned to 0xAA by harness); memset is capturable
    cudaMemsetAsync(d_out, 0, (size_t)out_size * sizeof(float));

    // 2) scatter-add: 8 lanes per edge, 4 fragments per thread (grid-stride)
    int num_frags = num_edges * 8;                       // 12.8M
    int threads = 256;
    long long total_threads = ((long long)num_frags + UNROLL - 1) / UNROLL;
    int blocks = (int)((total_threads + threads - 1) / threads);   // 12500 exact
    scatter_add_kernel<<<blocks, threads>>>(msg4, tgt, out, num_frags);
}

// round 15
// speedup vs baseline: 1.0047x; 1.0047x over previous
#include <cuda_runtime.h>
#include <cstdint>

// GCNStage4_ReduceSum: out[t] += msg[e] for t = edge_index[1][e]
// msg: [NUM_EDGES, 32] f32; edge_index: [2, NUM_EDGES] int32 (harness); out: [num_nodes, 32] f32
//
// FINAL (converged, re-verified x4): atomic scatter at the validated sm_103a
// L2 fp-RMW roofline. Session evidence:
//   - 7 structural variants (MLP sweep, occupancy sweep, lane relayout,
//     software pipeline, ELL gather, TMA cp.reduce.async.bulk, hybrid
//     concurrent paths) all converge to the ~46.3us scatter wall.
//   - Wall = 12.8M x 16B fp-add RMW micro-ops at the shared L2 atomic ALU
//     (bulk-TMA framing decomposes to the same micro-ops: R11 hybrid flat).
//   - DRAM traffic measured == compulsory 228MB; no wasted bytes.
//   - This exact shape holds the best scatter time (46.24us, reproduced) and
//     best totals (47.584us x2); run-to-run spread ~0.3us is harness noise.
//   - Residual ~1.5us = semantically-required zero-fill (12.8MB) + launch
//     overhead; fusion alternatives cost more than they save (grid-sync).
//
// Shape: 8 lanes = one 128B edge row (RED.128 warp-op touches 4 lines),
// unroll-4 grid-stride with front-batched loads (MLP~8 per thread),
// fire-and-forget red.global.add.v4.f32, cudaMemsetAsync zero-fill.

#define FEAT 32
#define UNROLL 4

__global__ void __launch_bounds__(256) scatter_add_kernel(
        const float4* __restrict__ msg4,
        const int* __restrict__ tgt,
        float* __restrict__ out,
        int num_frags)   // num_edges * 8
{
    int tid = blockIdx.x * blockDim.x + threadIdx.x;
    int stride = gridDim.x * blockDim.x;

    int   t[UNROLL];
    float4 v[UNROLL];
    int   id[UNROLL];

    // Phase 1: issue all loads (front-batched -> high MLP)
    #pragma unroll
    for (int u = 0; u < UNROLL; u++) {
        id[u] = tid + u * stride;
        if (id[u] < num_frags) {
            int e   = id[u] >> 3;
            int sub = id[u] & 7;
            t[u] = tgt[e];                                   // broadcast across 8 lanes
            v[u] = __ldcs(&msg4[(size_t)e * 8 + sub]);       // coalesced 128B row
        }
    }

    // Phase 2: fire-and-forget vector reductions (resolve at L2)
    #pragma unroll
    for (int u = 0; u < UNROLL; u++) {
        if (id[u] < num_frags) {
            int sub = id[u] & 7;
            float* dst = out + (size_t)t[u] * FEAT + sub * 4;
            asm volatile("red.global.add.v4.f32 [%0], {%1, %2, %3, %4};"
                         :: "l"(dst), "f"(v[u].x), "f"(v[u].y), "f"(v[u].z), "f"(v[u].w)
                         : "memory");
        }
    }
}

extern "C" void kernel_launch(void* const* d_in, const int* in_sizes, int n_in,
                              void* d_out, int out_size) {
    const float4* msg4 = (const float4*)d_in[0];
    const int*    ei   = (const int*)d_in[1];   // int32 indices
    float*        out  = (float*)d_out;

    int num_edges = in_sizes[0] / FEAT;          // 1,600,000
    const int* tgt = ei + num_edges;             // row 1 of edge_index

    // 1) zero the output (poisoned to 0xAA by harness); memset is capturable
    cudaMemsetAsync(d_out, 0, (size_t)out_size * sizeof(float));

    // 2) scatter-add: 8 lanes per edge, 4 fragments per thread (grid-stride)
    int num_frags = num_edges * 8;                       // 12.8M
    int threads = 256;
    long long total_threads = ((long long)num_frags + UNROLL - 1) / UNROLL;
    int blocks = (int)((total_threads + threads - 1) / threads);   // 12500 exact
    scatter_add_kernel<<<blocks, threads>>>(msg4, tgt, out, num_frags);
}

// round 16
// speedup vs baseline: 1.0054x; 1.0007x over previous
#include <cuda_runtime.h>
#include <cstdint>

// GCNStage4_ReduceSum: out[t] += msg[e] for t = edge_index[1][e]
// msg: [NUM_EDGES, 32] f32; edge_index: [2, NUM_EDGES] int32 (harness); out: [num_nodes, 32] f32
//
// FINAL (converged, re-verified x5): atomic scatter at the validated sm_103a
// L2 fp-RMW roofline. Session evidence:
//   - 7 structural variants (MLP sweep, occupancy sweep, lane relayout,
//     software pipeline, ELL gather, TMA cp.reduce.async.bulk, hybrid
//     concurrent paths) all converge to the ~46.2us scatter wall.
//   - Wall = 12.8M x 16B fp-add RMW micro-ops at the shared L2 atomic ALU
//     (bulk-TMA framing decomposes to the same micro-ops: R11 hybrid flat).
//   - DRAM traffic measured == compulsory 228MB; no wasted bytes.
//   - This shape holds best scatter (46.02us) and best totals (47.584us x2);
//     run-to-run spread ~0.3us is harness noise.
//   - Residual ~1.6us = semantically-required zero-fill (12.8MB, strict
//     ordering before RMWs) + graph replay overhead; no fusion wins.
//
// Shape: 8 lanes = one 128B edge row (RED.128 warp-op touches 4 lines),
// unroll-4 grid-stride with front-batched loads (MLP~8 per thread),
// fire-and-forget red.global.add.v4.f32, cudaMemsetAsync zero-fill.

#define FEAT 32
#define UNROLL 4

__global__ void __launch_bounds__(256) scatter_add_kernel(
        const float4* __restrict__ msg4,
        const int* __restrict__ tgt,
        float* __restrict__ out,
        int num_frags)   // num_edges * 8
{
    int tid = blockIdx.x * blockDim.x + threadIdx.x;
    int stride = gridDim.x * blockDim.x;

    int   t[UNROLL];
    float4 v[UNROLL];
    int   id[UNROLL];

    // Phase 1: issue all loads (front-batched -> high MLP)
    #pragma unroll
    for (int u = 0; u < UNROLL; u++) {
        id[u] = tid + u * stride;
        if (id[u] < num_frags) {
            int e   = id[u] >> 3;
            int sub = id[u] & 7;
            t[u] = tgt[e];                                   // broadcast across 8 lanes
            v[u] = __ldcs(&msg4[(size_t)e * 8 + sub]);       // coalesced 128B row
        }
    }

    // Phase 2: fire-and-forget vector reductions (resolve at L2)
    #pragma unroll
    for (int u = 0; u < UNROLL; u++) {
        if (id[u] < num_frags) {
            int sub = id[u] & 7;
            float* dst = out + (size_t)t[u] * FEAT + sub * 4;
            asm volatile("red.global.add.v4.f32 [%0], {%1, %2, %3, %4};"
                         :: "l"(dst), "f"(v[u].x), "f"(v[u].y), "f"(v[u].z), "f"(v[u].w)
                         : "memory");
        }
    }
}

extern "C" void kernel_launch(void* const* d_in, const int* in_sizes, int n_in,
                              void* d_out, int out_size) {
    const float4* msg4 = (const float4*)d_in[0];
    const int*    ei   = (const int*)d_in[1];   // int32 indices
    float*        out  = (float*)d_out;

    int num_edges = in_sizes[0] / FEAT;          // 1,600,000
    const int* tgt = ei + num_edges;             // row 1 of edge_index

    // 1) zero the output (poisoned to 0xAA by harness); memset is capturable
    cudaMemsetAsync(d_out, 0, (size_t)out_size * sizeof(float));

    // 2) scatter-add: 8 lanes per edge, 4 fragments per thread (grid-stride)
    int num_frags = num_edges * 8;                       // 12.8M
    int threads = 256;
    long long total_threads = ((long long)num_frags + UNROLL - 1) / UNROLL;
    int blocks = (int)((total_threads + threads - 1) / threads);   // 12500 exact
    scatter_add_kernel<<<blocks, threads>>>(msg4, tgt, out, num_frags);
}